// round 5
// baseline (speedup 1.0000x reference)
#include <cuda_runtime.h>
#include <cuda_fp16.h>
#include <cstdint>
#include <math.h>

#define N_SPK 2048
#define M_UTT 16
#define D_DIM 128
#define ROWS  32768

#define BM 256                  // rows per CTA
#define BN 128                  // centroid cols per chunk
#define NCTA (ROWS / BM)        // 128
#define NCHUNK (N_SPK / BN)     // 16
#define THREADS 256

#define A_U4 (16 * 8 * 32)      // per-CTA packed A uint4 count = 4096 (64KB)
#define STAGE_U4 2048           // 32KB per B chunk stage
#define DYN_SMEM (A_U4 * 16 + 2 * STAGE_U4 * 16)   // 131072

// packed fp16 operands in fragment order (__device__ scratch; no cudaMalloc)
__device__ uint4 gAh[NCTA * A_U4];               // 8MB
__device__ uint4 gBh[NCHUNK * STAGE_U4];         // 512KB
__device__ float g_partial[NCTA];
__device__ unsigned g_ctr = 0;

// ---------------------------------------------------------------------------
__device__ __forceinline__ uint32_t smem_u32(const void* p) {
    uint32_t a;
    asm("{ .reg .u64 t; cvta.to.shared.u64 t, %1; cvt.u32.u64 %0, t; }" : "=r"(a) : "l"(p));
    return a;
}
__device__ __forceinline__ void cp_async16(uint32_t dst, const void* src) {
    asm volatile("cp.async.cg.shared.global [%0], [%1], 16;" :: "r"(dst), "l"(src));
}
#define CP_COMMIT() asm volatile("cp.async.commit_group;" ::: "memory")
#define CP_WAIT0()  asm volatile("cp.async.wait_group 0;" ::: "memory")
#define CP_WAIT1()  asm volatile("cp.async.wait_group 1;" ::: "memory")

__device__ __forceinline__ uint32_t pack2(float lo, float hi) {
    __half2 h = __floats2half2_rn(lo, hi);
    return *reinterpret_cast<uint32_t*>(&h);
}
__device__ __forceinline__ float ex2(float x) {
    float y;
    asm("ex2.approx.f32 %0, %1;" : "=f"(y) : "f"(x));
    return y;
}

// d += a * b  (m16n8k16 f16 -> f32)
#define MMA(d, a, b0, b1) \
    asm volatile("mma.sync.aligned.m16n8k16.row.col.f32.f16.f16.f32 " \
                 "{%0,%1,%2,%3},{%4,%5,%6,%7},{%8,%9},{%0,%1,%2,%3};" \
                 : "+f"((d)[0]), "+f"((d)[1]), "+f"((d)[2]), "+f"((d)[3]) \
                 : "r"((a).x), "r"((a).y), "r"((a).z), "r"((a).w), "r"(b0), "r"(b1))

// ---------------------------------------------------------------------------
// Pre-kernel 1: pack x -> A fragments (fp16).  id = [cta7][mt4][ks3][lane5]
// ---------------------------------------------------------------------------
__global__ __launch_bounds__(256) void pack_a_kernel(const float* __restrict__ x) {
    int id = blockIdx.x * 256 + threadIdx.x;        // 0..524287
    int lane = id & 31, ks = (id >> 5) & 7, mt = (id >> 8) & 15, cta = id >> 12;
    int g = lane >> 2, t = lane & 3;
    int r0 = cta * BM + mt * 16 + g;
    int k0 = ks * 16 + t * 2;
    const float* p0 = x + (size_t)r0 * D_DIM;
    const float* p1 = p0 + 8 * D_DIM;
    float2 alo = *(const float2*)(p0 + k0);
    float2 blo = *(const float2*)(p1 + k0);
    float2 ahi = *(const float2*)(p0 + k0 + 8);
    float2 bhi = *(const float2*)(p1 + k0 + 8);
    uint4 o;
    o.x = pack2(alo.x, alo.y);
    o.y = pack2(blo.x, blo.y);
    o.z = pack2(ahi.x, ahi.y);
    o.w = pack2(bhi.x, bhi.y);
    gAh[id] = o;
}

// ---------------------------------------------------------------------------
// Pre-kernel 2: centroid + pack B fragments, fused. id = [c4][ks3][pp3][lane5]
// ---------------------------------------------------------------------------
__global__ __launch_bounds__(256) void pack_b_kernel(const float* __restrict__ x) {
    int id = blockIdx.x * 256 + threadIdx.x;        // 0..32767
    int lane = id & 31, pp = (id >> 5) & 7, ks = (id >> 8) & 7, c = id >> 11;
    int g = lane >> 2, t = lane & 3;
    int col0 = c * BN + pp * 16 + g;
    int k0 = ks * 16 + t * 2;
    const float* base0 = x + (size_t)col0 * M_UTT * D_DIM;
    const float* base1 = base0 + (size_t)8 * M_UTT * D_DIM;
    float2 s0l = {0.f, 0.f}, s0h = {0.f, 0.f}, s1l = {0.f, 0.f}, s1h = {0.f, 0.f};
#pragma unroll
    for (int m = 0; m < M_UTT; m++) {
        const float* r0 = base0 + m * D_DIM;
        const float* r1 = base1 + m * D_DIM;
        float2 v;
        v = *(const float2*)(r0 + k0);     s0l.x += v.x; s0l.y += v.y;
        v = *(const float2*)(r0 + k0 + 8); s0h.x += v.x; s0h.y += v.y;
        v = *(const float2*)(r1 + k0);     s1l.x += v.x; s1l.y += v.y;
        v = *(const float2*)(r1 + k0 + 8); s1h.x += v.x; s1h.y += v.y;
    }
    const float inv = 1.0f / M_UTT;
    uint4 o;
    o.x = pack2(s0l.x * inv, s0l.y * inv);
    o.y = pack2(s0h.x * inv, s0h.y * inv);
    o.z = pack2(s1l.x * inv, s1l.y * inv);
    o.w = pack2(s1h.x * inv, s1h.y * inv);
    gBh[id] = o;
}

// ---------------------------------------------------------------------------
__device__ __forceinline__ void load_stage(uint32_t dst, int c, int tid) {
    const uint4* src = gBh + (size_t)c * STAGE_U4;
#pragma unroll
    for (int i = 0; i < 8; i++) {
        int f = tid + i * 256;
        cp_async16(dst + f * 16, src + f);
    }
}

// epilogue of one 16x8 accumulator tile (4 elements), then zero it
__device__ __forceinline__ void epi4(float* A4, int col, int sp0v, int sp1v, int lr,
                                     float w2, float b2, float wd, float bd,
                                     float& r0, float& r1, float* s_tgt) {
    float v, l;
    v = A4[0]; l = fmaf(w2, v, b2);
    if (col == sp0v)     { l = fmaf(wd, v, bd); s_tgt[lr] = l; }
    r0 += ex2(l);
    v = A4[1]; l = fmaf(w2, v, b2);
    if (col + 1 == sp0v) { l = fmaf(wd, v, bd); s_tgt[lr] = l; }
    r0 += ex2(l);
    v = A4[2]; l = fmaf(w2, v, b2);
    if (col == sp1v)     { l = fmaf(wd, v, bd); s_tgt[lr + 8] = l; }
    r1 += ex2(l);
    v = A4[3]; l = fmaf(w2, v, b2);
    if (col + 1 == sp1v) { l = fmaf(wd, v, bd); s_tgt[lr + 8] = l; }
    r1 += ex2(l);
    A4[0] = 0.f; A4[1] = 0.f; A4[2] = 0.f; A4[3] = 0.f;
}

// one chunk: MMA half0 (nt0-3) || epi half1 of prev chunk; MMA half1 || epi half0
template<bool PREV>
__device__ __forceinline__ void do_chunk(const uint4* __restrict__ As,
                                         const uint4* __restrict__ Bst,
                                         float (&acc)[4][8][4], float (&rsum)[4][2],
                                         const int (&lrow)[4], const int (&sp0)[4],
                                         const int (&sp1)[4], float* s_tgt,
                                         int lane, int wm, int wn, int t4,
                                         int cb, int cbp,
                                         float w2, float b2, float wd, float bd) {
    // ---- pass A: MMA nt0..3, epi prev nt4..7 ----
#pragma unroll
    for (int s = 0; s < 8; s++) {
        uint4 a0 = As[((wm * 4 + 0) * 8 + s) * 32 + lane];
        uint4 a1 = As[((wm * 4 + 1) * 8 + s) * 32 + lane];
        uint4 a2 = As[((wm * 4 + 2) * 8 + s) * 32 + lane];
        uint4 a3 = As[((wm * 4 + 3) * 8 + s) * 32 + lane];
        uint4 b0 = Bst[(s * 8 + wn * 4 + 0) * 32 + lane];
        uint4 b1 = Bst[(s * 8 + wn * 4 + 1) * 32 + lane];
        MMA(acc[0][0], a0, b0.x, b0.y); MMA(acc[0][1], a0, b0.z, b0.w);
        MMA(acc[1][0], a1, b0.x, b0.y); MMA(acc[1][1], a1, b0.z, b0.w);
        MMA(acc[2][0], a2, b0.x, b0.y); MMA(acc[2][1], a2, b0.z, b0.w);
        MMA(acc[3][0], a3, b0.x, b0.y); MMA(acc[3][1], a3, b0.z, b0.w);
        MMA(acc[0][2], a0, b1.x, b1.y); MMA(acc[0][3], a0, b1.z, b1.w);
        MMA(acc[1][2], a1, b1.x, b1.y); MMA(acc[1][3], a1, b1.z, b1.w);
        MMA(acc[2][2], a2, b1.x, b1.y); MMA(acc[2][3], a2, b1.z, b1.w);
        MMA(acc[3][2], a3, b1.x, b1.y); MMA(acc[3][3], a3, b1.z, b1.w);
        if (PREV) {
#pragma unroll
            for (int u = 0; u < 2; u++) {
                const int tt = s * 2 + u;
                const int mt = tt >> 2, nt = 4 + (tt & 3);
                epi4(acc[mt][nt], cbp + nt * 8 + t4 * 2, sp0[mt], sp1[mt], lrow[mt],
                     w2, b2, wd, bd, rsum[mt][0], rsum[mt][1], s_tgt);
            }
        }
    }
    // ---- pass B: MMA nt4..7, epi this-chunk nt0..3 ----
#pragma unroll
    for (int s = 0; s < 8; s++) {
        uint4 a0 = As[((wm * 4 + 0) * 8 + s) * 32 + lane];
        uint4 a1 = As[((wm * 4 + 1) * 8 + s) * 32 + lane];
        uint4 a2 = As[((wm * 4 + 2) * 8 + s) * 32 + lane];
        uint4 a3 = As[((wm * 4 + 3) * 8 + s) * 32 + lane];
        uint4 b2q = Bst[(s * 8 + wn * 4 + 2) * 32 + lane];
        uint4 b3q = Bst[(s * 8 + wn * 4 + 3) * 32 + lane];
        MMA(acc[0][4], a0, b2q.x, b2q.y); MMA(acc[0][5], a0, b2q.z, b2q.w);
        MMA(acc[1][4], a1, b2q.x, b2q.y); MMA(acc[1][5], a1, b2q.z, b2q.w);
        MMA(acc[2][4], a2, b2q.x, b2q.y); MMA(acc[2][5], a2, b2q.z, b2q.w);
        MMA(acc[3][4], a3, b2q.x, b2q.y); MMA(acc[3][5], a3, b2q.z, b2q.w);
        MMA(acc[0][6], a0, b3q.x, b3q.y); MMA(acc[0][7], a0, b3q.z, b3q.w);
        MMA(acc[1][6], a1, b3q.x, b3q.y); MMA(acc[1][7], a1, b3q.z, b3q.w);
        MMA(acc[2][6], a2, b3q.x, b3q.y); MMA(acc[2][7], a2, b3q.z, b3q.w);
        MMA(acc[3][6], a3, b3q.x, b3q.y); MMA(acc[3][7], a3, b3q.z, b3q.w);
#pragma unroll
        for (int u = 0; u < 2; u++) {
            const int tt = s * 2 + u;
            const int mt = tt >> 2, nt = tt & 3;
            epi4(acc[mt][nt], cb + nt * 8 + t4 * 2, sp0[mt], sp1[mt], lrow[mt],
                 w2, b2, wd, bd, rsum[mt][0], rsum[mt][1], s_tgt);
        }
    }
}

// ---------------------------------------------------------------------------
// Main: fp16 mma.sync GEMM fused with log2-domain softmax reduction.
// 8 warps as 4(m) x 2(n); warp tile 64x64; MMA/epilogue software-pipelined.
// ---------------------------------------------------------------------------
__global__ __launch_bounds__(THREADS, 1) void ge2e_main(const float* __restrict__ wp,
                                                        const float* __restrict__ bp,
                                                        float* __restrict__ out) {
    extern __shared__ uint4 dsm[];
    __shared__ float s_tgt[BM];
    __shared__ float s_red[BM][2];
    __shared__ float s_loss[BM];
    __shared__ bool  s_last;

    const int tid  = threadIdx.x;
    const int wid  = tid >> 5;
    const int lane = tid & 31;
    const int wm = wid >> 1;
    const int wn = wid & 1;
    const int g  = lane >> 2;
    const int t4 = lane & 3;

    const float L2E = 1.44269504088896341f;
    const float w2  = wp[0] * L2E;
    const float b2  = bp[0] * L2E;
    const float wd  = w2 * (16.0f / 15.0f);
    const float bd  = b2 - w2 * (1.0f / 15.0f);

    const uint32_t smA  = smem_u32(dsm);
    const uint32_t smB0 = smA + A_U4 * 16;

    const uint4* gAs = gAh + (size_t)blockIdx.x * A_U4;
#pragma unroll
    for (int i = 0; i < 16; i++)
        cp_async16(smA + (tid + i * 256) * 16, gAs + tid + i * 256);
    load_stage(smB0, 0, tid);
    CP_COMMIT();
    load_stage(smB0 + STAGE_U4 * 16, 1, tid);
    CP_COMMIT();

    float acc[4][8][4];
#pragma unroll
    for (int mt = 0; mt < 4; mt++)
#pragma unroll
        for (int nt = 0; nt < 8; nt++)
#pragma unroll
            for (int q = 0; q < 4; q++) acc[mt][nt][q] = 0.f;

    float rsum[4][2] = {};
    int lrow[4], sp0[4], sp1[4];
#pragma unroll
    for (int mt = 0; mt < 4; mt++) {
        lrow[mt] = wm * 64 + mt * 16 + g;
        int gr = blockIdx.x * BM + lrow[mt];
        sp0[mt] = gr >> 4;
        sp1[mt] = (gr + 8) >> 4;
    }

    for (int c = 0; c < NCHUNK; c++) {
        if (c == NCHUNK - 1) CP_WAIT0(); else CP_WAIT1();
        __syncthreads();

        const uint4* Bst = dsm + A_U4 + (c & 1) * STAGE_U4;
        const int cb  = c * BN + wn * 64;
        const int cbp = (c - 1) * BN + wn * 64;
        if (c == 0)
            do_chunk<false>(dsm, Bst, acc, rsum, lrow, sp0, sp1, s_tgt,
                            lane, wm, wn, t4, cb, cbp, w2, b2, wd, bd);
        else
            do_chunk<true>(dsm, Bst, acc, rsum, lrow, sp0, sp1, s_tgt,
                           lane, wm, wn, t4, cb, cbp, w2, b2, wd, bd);

        __syncthreads();
        if (c + 2 < NCHUNK) {
            load_stage(smB0 + (c & 1) * (STAGE_U4 * 16), c + 2, tid);
            CP_COMMIT();
        }
    }

    // drain: epilogue of last chunk's half1
    {
        const int cb = (NCHUNK - 1) * BN + wn * 64;
#pragma unroll
        for (int mt = 0; mt < 4; mt++)
#pragma unroll
            for (int nt = 4; nt < 8; nt++)
                epi4(acc[mt][nt], cb + nt * 8 + t4 * 2, sp0[mt], sp1[mt], lrow[mt],
                     w2, b2, wd, bd, rsum[mt][0], rsum[mt][1], s_tgt);
    }

    // reduce 4 t4-lanes per row, then the 2 n-warps
#pragma unroll
    for (int mt = 0; mt < 4; mt++)
#pragma unroll
        for (int hh = 0; hh < 2; hh++) {
            float v = rsum[mt][hh];
            v += __shfl_xor_sync(0xFFFFFFFFu, v, 1);
            v += __shfl_xor_sync(0xFFFFFFFFu, v, 2);
            if (t4 == 0) s_red[lrow[mt] + hh * 8][wn] = v;
        }
    __syncthreads();
    if (tid < BM) {
        float S = s_red[tid][0] + s_red[tid][1];
        s_loss[tid] = (log2f(S) - s_tgt[tid]) * 0.69314718055994531f;
    }
    __syncthreads();
    if (tid == 0) {
        float L = 0.f;
#pragma unroll 8
        for (int r = 0; r < BM; r++) L += s_loss[r];
        g_partial[blockIdx.x] = L;
        __threadfence();
        unsigned old = atomicAdd(&g_ctr, 1u);
        s_last = (old == NCTA - 1);
    }
    __syncthreads();

    if (s_last) {
        if (tid == 0) g_ctr = 0;
        __threadfence();
        if (tid < NCTA) s_loss[tid] = g_partial[tid];
        __syncthreads();
        for (int o = NCTA / 2; o > 0; o >>= 1) {
            if (tid < o && tid + o < NCTA) s_loss[tid] += s_loss[tid + o];
            __syncthreads();
        }
        if (tid == 0) out[0] = s_loss[0] * (1.0f / (float)ROWS);
    }
}

extern "C" void kernel_launch(void* const* d_in, const int* in_sizes, int n_in,
                              void* d_out, int out_size) {
    const float* x = (const float*)d_in[0];
    const float* w = (const float*)d_in[1];
    const float* b = (const float*)d_in[2];
    float* out = (float*)d_out;

    cudaFuncSetAttribute(ge2e_main, cudaFuncAttributeMaxDynamicSharedMemorySize, DYN_SMEM);

    pack_a_kernel<<<(NCTA * A_U4) / 256, 256>>>(x);
    pack_b_kernel<<<(NCHUNK * STAGE_U4) / 256, 256>>>(x);
    ge2e_main<<<NCTA, THREADS, DYN_SMEM>>>(w, b, out);
}

// round 6
// speedup vs baseline: 1.1254x; 1.1254x over previous
#include <cuda_runtime.h>
#include <cuda_fp16.h>
#include <cstdint>
#include <math.h>

#define N_SPK 2048
#define M_UTT 16
#define D_DIM 128
#define ROWS  32768

#define BM 128                  // rows per CTA
#define BN 128                  // centroid cols per chunk
#define NCTA (ROWS / BM)        // 256
#define NCHUNK (N_SPK / BN)     // 16
#define THREADS 256

#define A_U4 (8 * 8 * 32)       // per-CTA packed A uint4 = 2048 (32KB)
#define STAGE_U4 2048           // 32KB per B chunk stage
#define DYN_SMEM (A_U4 * 16 + 2 * STAGE_U4 * 16)   // 98304

// packed fp16 operands in fragment order (__device__ scratch; no cudaMalloc)
__device__ uint4 gAh[NCTA * A_U4];               // 8MB
__device__ uint4 gBh[NCHUNK * STAGE_U4];         // 512KB
__device__ float g_partial[NCTA];
__device__ unsigned g_ctr = 0;

// ---------------------------------------------------------------------------
__device__ __forceinline__ uint32_t smem_u32(const void* p) {
    uint32_t a;
    asm("{ .reg .u64 t; cvta.to.shared.u64 t, %1; cvt.u32.u64 %0, t; }" : "=r"(a) : "l"(p));
    return a;
}
__device__ __forceinline__ void cp_async16(uint32_t dst, const void* src) {
    asm volatile("cp.async.cg.shared.global [%0], [%1], 16;" :: "r"(dst), "l"(src));
}
#define CP_COMMIT() asm volatile("cp.async.commit_group;" ::: "memory")
#define CP_WAIT0()  asm volatile("cp.async.wait_group 0;" ::: "memory")
#define CP_WAIT1()  asm volatile("cp.async.wait_group 1;" ::: "memory")

__device__ __forceinline__ uint32_t pack2(float lo, float hi) {
    __half2 h = __floats2half2_rn(lo, hi);
    return *reinterpret_cast<uint32_t*>(&h);
}
__device__ __forceinline__ float ex2(float x) {
    float y;
    asm("ex2.approx.f32 %0, %1;" : "=f"(y) : "f"(x));
    return y;
}

// d += a * b
#define MMA(d, a, b0, b1) \
    asm volatile("mma.sync.aligned.m16n8k16.row.col.f32.f16.f16.f32 " \
                 "{%0,%1,%2,%3},{%4,%5,%6,%7},{%8,%9},{%0,%1,%2,%3};" \
                 : "+f"((d)[0]), "+f"((d)[1]), "+f"((d)[2]), "+f"((d)[3]) \
                 : "r"((a).x), "r"((a).y), "r"((a).z), "r"((a).w), "r"(b0), "r"(b1))
// d = a * b   (no accumulate -> kills per-chunk zeroing)
#define MMA_INIT(d, a, b0, b1) \
    asm volatile("mma.sync.aligned.m16n8k16.row.col.f32.f16.f16.f32 " \
                 "{%0,%1,%2,%3},{%4,%5,%6,%7},{%8,%9},{%10,%10,%10,%10};" \
                 : "=f"((d)[0]), "=f"((d)[1]), "=f"((d)[2]), "=f"((d)[3]) \
                 : "r"((a).x), "r"((a).y), "r"((a).z), "r"((a).w), "r"(b0), "r"(b1), "f"(0.f))

// ---------------------------------------------------------------------------
// Pre-kernel 1: pack x -> A fragments.  id = [cta8][mt3][ks3][lane5]
// ---------------------------------------------------------------------------
__global__ __launch_bounds__(256) void pack_a_kernel(const float* __restrict__ x) {
    int id = blockIdx.x * 256 + threadIdx.x;        // 0..524287
    int lane = id & 31, ks = (id >> 5) & 7, mt = (id >> 8) & 7, cta = id >> 11;
    int g = lane >> 2, t = lane & 3;
    int r0 = cta * BM + mt * 16 + g;
    int k0 = ks * 16 + t * 2;
    const float* p0 = x + (size_t)r0 * D_DIM;
    const float* p1 = p0 + 8 * D_DIM;
    float2 alo = *(const float2*)(p0 + k0);
    float2 blo = *(const float2*)(p1 + k0);
    float2 ahi = *(const float2*)(p0 + k0 + 8);
    float2 bhi = *(const float2*)(p1 + k0 + 8);
    uint4 o;
    o.x = pack2(alo.x, alo.y);
    o.y = pack2(blo.x, blo.y);
    o.z = pack2(ahi.x, ahi.y);
    o.w = pack2(bhi.x, bhi.y);
    gAh[id] = o;
}

// ---------------------------------------------------------------------------
// Pre-kernel 2: centroid + pack B fragments.  id = [c4][ks3][pp3][lane5]
// ---------------------------------------------------------------------------
__global__ __launch_bounds__(256) void pack_b_kernel(const float* __restrict__ x) {
    int id = blockIdx.x * 256 + threadIdx.x;        // 0..32767
    int lane = id & 31, pp = (id >> 5) & 7, ks = (id >> 8) & 7, c = id >> 11;
    int g = lane >> 2, t = lane & 3;
    int col0 = c * BN + pp * 16 + g;
    int k0 = ks * 16 + t * 2;
    const float* base0 = x + (size_t)col0 * M_UTT * D_DIM;
    const float* base1 = base0 + (size_t)8 * M_UTT * D_DIM;
    float2 s0l = {0.f, 0.f}, s0h = {0.f, 0.f}, s1l = {0.f, 0.f}, s1h = {0.f, 0.f};
#pragma unroll
    for (int m = 0; m < M_UTT; m++) {
        const float* r0 = base0 + m * D_DIM;
        const float* r1 = base1 + m * D_DIM;
        float2 v;
        v = *(const float2*)(r0 + k0);     s0l.x += v.x; s0l.y += v.y;
        v = *(const float2*)(r0 + k0 + 8); s0h.x += v.x; s0h.y += v.y;
        v = *(const float2*)(r1 + k0);     s1l.x += v.x; s1l.y += v.y;
        v = *(const float2*)(r1 + k0 + 8); s1h.x += v.x; s1h.y += v.y;
    }
    const float inv = 1.0f / M_UTT;
    uint4 o;
    o.x = pack2(s0l.x * inv, s0l.y * inv);
    o.y = pack2(s0h.x * inv, s0h.y * inv);
    o.z = pack2(s1l.x * inv, s1l.y * inv);
    o.w = pack2(s1h.x * inv, s1h.y * inv);
    gBh[id] = o;
}

// ---------------------------------------------------------------------------
__device__ __forceinline__ void load_stage(uint32_t dst, int c, int tid) {
    const uint4* src = gBh + (size_t)c * STAGE_U4;
#pragma unroll
    for (int i = 0; i < 8; i++) {
        int f = tid + i * 256;
        cp_async16(dst + f * 16, src + f);
    }
}

// ---------------------------------------------------------------------------
// Main: fp16 mma.sync GEMM + log2-domain softmax reduction. BM=128, 2 CTA/SM.
// 8 warps as 4(m) x 2(n); warp tile 32x64.
// ---------------------------------------------------------------------------
__global__ __launch_bounds__(THREADS, 2) void ge2e_main(const float* __restrict__ wp,
                                                        const float* __restrict__ bp,
                                                        float* __restrict__ out) {
    extern __shared__ uint4 dsm[];
    __shared__ float s_tgt[BM];
    __shared__ float s_red[BM][2];
    __shared__ float s_loss[BM];
    __shared__ bool  s_last;

    const int tid  = threadIdx.x;
    const int wid  = tid >> 5;
    const int lane = tid & 31;
    const int wm = wid >> 1;            // 0..3
    const int wn = wid & 1;             // 0..1
    const int g  = lane >> 2;
    const int t4 = lane & 3;

    const float L2E = 1.44269504088896341f;
    const float w2  = wp[0] * L2E;
    const float b2  = bp[0] * L2E;
    const float wd  = w2 * (16.0f / 15.0f);
    const float bd  = b2 - w2 * (1.0f / 15.0f);

    const uint32_t smA  = smem_u32(dsm);
    const uint32_t smB0 = smA + A_U4 * 16;
    const int c_diag = blockIdx.x >> 4;       // chunk holding all self-speaker cols

    const uint4* gAs = gAh + (size_t)blockIdx.x * A_U4;
#pragma unroll
    for (int i = 0; i < 8; i++)
        cp_async16(smA + (tid + i * 256) * 16, gAs + tid + i * 256);
    load_stage(smB0, 0, tid);
    CP_COMMIT();
    load_stage(smB0 + STAGE_U4 * 16, 1, tid);
    CP_COMMIT();

    float acc[2][8][4];
    float rsum[2][2] = {};
    int lrow[2], sp0[2], sp1[2];
#pragma unroll
    for (int mt = 0; mt < 2; mt++) {
        lrow[mt] = wm * 32 + mt * 16 + g;
        int gr = blockIdx.x * BM + lrow[mt];
        sp0[mt] = gr >> 4;
        sp1[mt] = (gr + 8) >> 4;
    }

    for (int c = 0; c < NCHUNK; c++) {
        if (c == NCHUNK - 1) CP_WAIT0(); else CP_WAIT1();
        __syncthreads();

        const uint4* Bst = dsm + A_U4 + (c & 1) * STAGE_U4;
        // ---- MMA pass ----
#pragma unroll
        for (int s = 0; s < 8; s++) {
            uint4 a0 = dsm[((wm * 2 + 0) * 8 + s) * 32 + lane];
            uint4 a1 = dsm[((wm * 2 + 1) * 8 + s) * 32 + lane];
            uint4 q0 = Bst[(s * 8 + wn * 4 + 0) * 32 + lane];
            uint4 q1 = Bst[(s * 8 + wn * 4 + 1) * 32 + lane];
            uint4 q2 = Bst[(s * 8 + wn * 4 + 2) * 32 + lane];
            uint4 q3 = Bst[(s * 8 + wn * 4 + 3) * 32 + lane];
            if (s == 0) {
                MMA_INIT(acc[0][0], a0, q0.x, q0.y); MMA_INIT(acc[0][1], a0, q0.z, q0.w);
                MMA_INIT(acc[1][0], a1, q0.x, q0.y); MMA_INIT(acc[1][1], a1, q0.z, q0.w);
                MMA_INIT(acc[0][2], a0, q1.x, q1.y); MMA_INIT(acc[0][3], a0, q1.z, q1.w);
                MMA_INIT(acc[1][2], a1, q1.x, q1.y); MMA_INIT(acc[1][3], a1, q1.z, q1.w);
                MMA_INIT(acc[0][4], a0, q2.x, q2.y); MMA_INIT(acc[0][5], a0, q2.z, q2.w);
                MMA_INIT(acc[1][4], a1, q2.x, q2.y); MMA_INIT(acc[1][5], a1, q2.z, q2.w);
                MMA_INIT(acc[0][6], a0, q3.x, q3.y); MMA_INIT(acc[0][7], a0, q3.z, q3.w);
                MMA_INIT(acc[1][6], a1, q3.x, q3.y); MMA_INIT(acc[1][7], a1, q3.z, q3.w);
            } else {
                MMA(acc[0][0], a0, q0.x, q0.y); MMA(acc[0][1], a0, q0.z, q0.w);
                MMA(acc[1][0], a1, q0.x, q0.y); MMA(acc[1][1], a1, q0.z, q0.w);
                MMA(acc[0][2], a0, q1.x, q1.y); MMA(acc[0][3], a0, q1.z, q1.w);
                MMA(acc[1][2], a1, q1.x, q1.y); MMA(acc[1][3], a1, q1.z, q1.w);
                MMA(acc[0][4], a0, q2.x, q2.y); MMA(acc[0][5], a0, q2.z, q2.w);
                MMA(acc[1][4], a1, q2.x, q2.y); MMA(acc[1][5], a1, q2.z, q2.w);
                MMA(acc[0][6], a0, q3.x, q3.y); MMA(acc[0][7], a0, q3.z, q3.w);
                MMA(acc[1][6], a1, q3.x, q3.y); MMA(acc[1][7], a1, q3.z, q3.w);
            }
        }
        __syncthreads();
        if (c + 2 < NCHUNK) {               // prefetch lands under the epilogue
            load_stage(smB0 + (c & 1) * (STAGE_U4 * 16), c + 2, tid);
            CP_COMMIT();
        }

        // ---- epilogue ----
        if (c == c_diag) {                  // the one chunk with self-speaker cols
#pragma unroll
            for (int mt = 0; mt < 2; mt++) {
#pragma unroll
                for (int nt = 0; nt < 8; nt++) {
                    const int col = c * BN + wn * 64 + nt * 8 + t4 * 2;
                    float* A4 = acc[mt][nt];
                    float v, l;
                    v = A4[0]; l = fmaf(w2, v, b2);
                    if (col == sp0[mt])     { l = fmaf(wd, v, bd); s_tgt[lrow[mt]] = l; }
                    rsum[mt][0] += ex2(l);
                    v = A4[1]; l = fmaf(w2, v, b2);
                    if (col + 1 == sp0[mt]) { l = fmaf(wd, v, bd); s_tgt[lrow[mt]] = l; }
                    rsum[mt][0] += ex2(l);
                    v = A4[2]; l = fmaf(w2, v, b2);
                    if (col == sp1[mt])     { l = fmaf(wd, v, bd); s_tgt[lrow[mt] + 8] = l; }
                    rsum[mt][1] += ex2(l);
                    v = A4[3]; l = fmaf(w2, v, b2);
                    if (col + 1 == sp1[mt]) { l = fmaf(wd, v, bd); s_tgt[lrow[mt] + 8] = l; }
                    rsum[mt][1] += ex2(l);
                }
            }
        } else {                            // compare-free fast path (15/16 chunks)
#pragma unroll
            for (int mt = 0; mt < 2; mt++) {
                float r0 = 0.f, r1 = 0.f;
#pragma unroll
                for (int nt = 0; nt < 8; nt++) {
                    float* A4 = acc[mt][nt];
                    r0 += ex2(fmaf(w2, A4[0], b2));
                    r0 += ex2(fmaf(w2, A4[1], b2));
                    r1 += ex2(fmaf(w2, A4[2], b2));
                    r1 += ex2(fmaf(w2, A4[3], b2));
                }
                rsum[mt][0] += r0;
                rsum[mt][1] += r1;
            }
        }
    }

    // reduce 4 t4-lanes per row, then the 2 n-warps
#pragma unroll
    for (int mt = 0; mt < 2; mt++)
#pragma unroll
        for (int hh = 0; hh < 2; hh++) {
            float v = rsum[mt][hh];
            v += __shfl_xor_sync(0xFFFFFFFFu, v, 1);
            v += __shfl_xor_sync(0xFFFFFFFFu, v, 2);
            if (t4 == 0) s_red[lrow[mt] + hh * 8][wn] = v;
        }
    __syncthreads();
    if (tid < BM) {
        float S = s_red[tid][0] + s_red[tid][1];
        s_loss[tid] = (log2f(S) - s_tgt[tid]) * 0.69314718055994531f;
    }
    __syncthreads();
    if (tid == 0) {
        float L = 0.f;
#pragma unroll 8
        for (int r = 0; r < BM; r++) L += s_loss[r];
        g_partial[blockIdx.x] = L;
        __threadfence();
        unsigned old = atomicAdd(&g_ctr, 1u);
        s_last = (old == NCTA - 1);
    }
    __syncthreads();

    if (s_last) {                           // last CTA: deterministic final reduce
        if (tid == 0) g_ctr = 0;
        __threadfence();
        float v = g_partial[tid];
        s_loss[tid & 127] = 0.f;            // reuse as 128-wide buffer
        __syncthreads();
        // 256 partials -> 128
        if (tid < 128) s_loss[tid] = g_partial[tid] + g_partial[tid + 128];
        __syncthreads();
        for (int o = 64; o > 0; o >>= 1) {
            if (tid < o) s_loss[tid] += s_loss[tid + o];
            __syncthreads();
        }
        if (tid == 0) out[0] = s_loss[0] * (1.0f / (float)ROWS);
        (void)v;
    }
}

extern "C" void kernel_launch(void* const* d_in, const int* in_sizes, int n_in,
                              void* d_out, int out_size) {
    const float* x = (const float*)d_in[0];
    const float* w = (const float*)d_in[1];
    const float* b = (const float*)d_in[2];
    float* out = (float*)d_out;

    cudaFuncSetAttribute(ge2e_main, cudaFuncAttributeMaxDynamicSharedMemorySize, DYN_SMEM);

    pack_a_kernel<<<(NCTA * A_U4) / 256, 256>>>(x);
    pack_b_kernel<<<(NCHUNK * STAGE_U4) / 256, 256>>>(x);
    ge2e_main<<<NCTA, THREADS, DYN_SMEM>>>(w, b, out);
}